// round 1
// baseline (speedup 1.0000x reference)
#include <cuda_runtime.h>
#include <math.h>

#define D_MODEL 1024
#define NHEAD   16
#define DKDIM   64
#define D_FC    4096
#define BATCH   2
#define SEQ     1024
#define EPSV    1e-6f
#define ROWS    (BATCH*SEQ)

// ---------------- static device scratch (no allocations allowed) ----------------
__device__ float g_xn [(size_t)ROWS * D_MODEL];
__device__ float g_q  [(size_t)ROWS * D_MODEL];
__device__ float g_k  [(size_t)ROWS * D_MODEL];
__device__ float g_v  [(size_t)ROWS * D_MODEL];
__device__ float g_att[(size_t)ROWS * D_MODEL];
__device__ float g_x1 [(size_t)ROWS * D_MODEL];
__device__ float g_ffh[(size_t)ROWS * D_FC];
__device__ float g_sc [(size_t)BATCH * NHEAD * SEQ * SEQ];   // 128 MB scores

// ---------------- block reductions ----------------
__device__ __forceinline__ float blockReduceSum(float v, float* sbuf) {
    __syncthreads();
    #pragma unroll
    for (int o = 16; o; o >>= 1) v += __shfl_down_sync(0xFFFFFFFFu, v, o);
    int lane = threadIdx.x & 31, w = threadIdx.x >> 5;
    if (lane == 0) sbuf[w] = v;
    __syncthreads();
    if (w == 0) {
        v = (lane < (int)(blockDim.x >> 5)) ? sbuf[lane] : 0.0f;
        #pragma unroll
        for (int o = 4; o; o >>= 1) v += __shfl_down_sync(0xFFFFFFFFu, v, o);
        if (lane == 0) sbuf[0] = v;
    }
    __syncthreads();
    return sbuf[0];
}

__device__ __forceinline__ float blockReduceMax(float v, float* sbuf) {
    __syncthreads();
    #pragma unroll
    for (int o = 16; o; o >>= 1) v = fmaxf(v, __shfl_down_sync(0xFFFFFFFFu, v, o));
    int lane = threadIdx.x & 31, w = threadIdx.x >> 5;
    if (lane == 0) sbuf[w] = v;
    __syncthreads();
    if (w == 0) {
        v = (lane < (int)(blockDim.x >> 5)) ? sbuf[lane] : -3.0e38f;
        #pragma unroll
        for (int o = 4; o; o >>= 1) v = fmaxf(v, __shfl_down_sync(0xFFFFFFFFu, v, o));
        if (lane == 0) sbuf[0] = v;
    }
    __syncthreads();
    return sbuf[0];
}

// ---------------- LayerNorm (torch semantics: ddof=1, /(std+eps)) ----------------
__global__ void __launch_bounds__(256) ln_kernel(const float* __restrict__ x,
                                                 const float* __restrict__ alpha,
                                                 const float* __restrict__ beta,
                                                 float* __restrict__ out) {
    __shared__ float sbuf[32];
    size_t row = blockIdx.x;
    const float4* xr = (const float4*)(x + row * D_MODEL);
    float4 v = xr[threadIdx.x];                      // 256 thr * 4 = 1024
    float s  = v.x + v.y + v.z + v.w;
    float sq = v.x*v.x + v.y*v.y + v.z*v.z + v.w*v.w;
    float sum   = blockReduceSum(s,  sbuf);
    float sumsq = blockReduceSum(sq, sbuf);
    float mean = sum * (1.0f / D_MODEL);
    float var  = (sumsq - sum * mean) * (1.0f / (D_MODEL - 1));
    float r = 1.0f / (sqrtf(fmaxf(var, 0.0f)) + EPSV);
    float4 a = ((const float4*)alpha)[threadIdx.x];
    float4 b = ((const float4*)beta )[threadIdx.x];
    float4 o;
    o.x = a.x * (v.x - mean) * r + b.x;
    o.y = a.y * (v.y - mean) * r + b.y;
    o.z = a.z * (v.z - mean) * r + b.z;
    o.w = a.w * (v.w - mean) * r + b.w;
    ((float4*)(out + row * D_MODEL))[threadIdx.x] = o;
}

// ---------------- masked softmax over score rows ----------------
__global__ void __launch_bounds__(256) softmax_kernel(float* __restrict__ sc,
                                                      const int* __restrict__ mask) {
    __shared__ float sbuf[32];
    size_t row = blockIdx.x;                   // over B*H*S rows
    int b = (int)(row / ((size_t)NHEAD * SEQ));
    float* p = sc + row * SEQ;
    const int* m = mask + (size_t)b * SEQ;
    int tid = threadIdx.x;
    float vals[4];
    float vmax = -3.0e38f;
    #pragma unroll
    for (int i = 0; i < 4; i++) {
        int kk = tid + i * 256;
        float v = m[kk] ? p[kk] : -1e9f;
        vals[i] = v;
        vmax = fmaxf(vmax, v);
    }
    vmax = blockReduceMax(vmax, sbuf);
    float sum = 0.0f;
    #pragma unroll
    for (int i = 0; i < 4; i++) {
        float e = __expf(vals[i] - vmax);
        vals[i] = e;
        sum += e;
    }
    sum = blockReduceSum(sum, sbuf);
    float inv = 1.0f / sum;
    #pragma unroll
    for (int i = 0; i < 4; i++) p[tid + i * 256] = vals[i] * inv;
}

// ---------------- tiled SGEMM: C = scale*(A @ op(B)) [+bias][relu][+resid] -------
// TRANSB=true : B is N x K row-major (C = A*B^T)    — weights, Q*K^T
// TRANSB=false: B is K x N row-major (C = A*B)      — attn*V
// Tiles: 128x64x16, 256 threads, 8x4 accumulators per thread.
#define BM 128
#define BN 64
#define BKT 16
#define TM 8
#define TN 4

template<bool TRANSB>
__global__ void __launch_bounds__(256) gemm_kernel(
    const float* __restrict__ A, int lda,
    const float* __restrict__ B, int ldb,
    float* __restrict__ C, int ldc,
    const float* __restrict__ bias,
    const float* __restrict__ resid, int ldr,
    int M, int N, int K, float scale, int relu,
    int Hdiv, size_t sAb, size_t sAh, size_t sBb, size_t sBh, size_t sCb, size_t sCh)
{
    __shared__ float As[BKT][BM];
    __shared__ float Bs[BKT][BN];

    if (gridDim.z > 1) {
        int z = blockIdx.z;
        int b = z / Hdiv, h = z - b * Hdiv;
        A += (size_t)b * sAb + (size_t)h * sAh;
        B += (size_t)b * sBb + (size_t)h * sBh;
        C += (size_t)b * sCb + (size_t)h * sCh;
    }

    int bm = blockIdx.y * BM;
    int bn = blockIdx.x * BN;
    int tid = threadIdx.x;
    int tx = tid & 15;        // 0..15 -> N
    int ty = tid >> 4;        // 0..15 -> M

    float acc[TM][TN];
    #pragma unroll
    for (int i = 0; i < TM; i++)
        #pragma unroll
        for (int j = 0; j < TN; j++) acc[i][j] = 0.0f;

    for (int k0 = 0; k0 < K; k0 += BKT) {
        // ---- load A tile (BM x BKT): 512 float4, 2 per thread
        #pragma unroll
        for (int i = 0; i < 2; i++) {
            int idx = tid * 2 + i;
            int row = idx >> 2;
            int kq  = (idx & 3) * 4;
            float4 va = *(const float4*)(A + (size_t)(bm + row) * lda + k0 + kq);
            As[kq + 0][row] = va.x;
            As[kq + 1][row] = va.y;
            As[kq + 2][row] = va.z;
            As[kq + 3][row] = va.w;
        }
        // ---- load B tile
        if (TRANSB) {
            int row = tid >> 2;           // 0..63 (n)
            int kq  = (tid & 3) * 4;
            float4 vb = *(const float4*)(B + (size_t)(bn + row) * ldb + k0 + kq);
            Bs[kq + 0][row] = vb.x;
            Bs[kq + 1][row] = vb.y;
            Bs[kq + 2][row] = vb.z;
            Bs[kq + 3][row] = vb.w;
        } else {
            int krow = tid >> 4;          // 0..15 (k)
            int nq   = (tid & 15) * 4;
            float4 vb = *(const float4*)(B + (size_t)(k0 + krow) * ldb + bn + nq);
            *(float4*)&Bs[krow][nq] = vb;
        }
        __syncthreads();

        #pragma unroll
        for (int kk = 0; kk < BKT; kk++) {
            float a[TM], b[TN];
            #pragma unroll
            for (int i = 0; i < TM; i++) a[i] = As[kk][ty * TM + i];
            #pragma unroll
            for (int j = 0; j < TN; j++) b[j] = Bs[kk][tx * TN + j];
            #pragma unroll
            for (int i = 0; i < TM; i++)
                #pragma unroll
                for (int j = 0; j < TN; j++) acc[i][j] += a[i] * b[j];
        }
        __syncthreads();
    }

    // ---- epilogue
    int row0 = bm + ty * TM;
    int col0 = bn + tx * TN;
    float4 bv = make_float4(0.f, 0.f, 0.f, 0.f);
    if (bias) bv = *(const float4*)(bias + col0);
    #pragma unroll
    for (int i = 0; i < TM; i++) {
        float4 o;
        o.x = acc[i][0] * scale + bv.x;
        o.y = acc[i][1] * scale + bv.y;
        o.z = acc[i][2] * scale + bv.z;
        o.w = acc[i][3] * scale + bv.w;
        if (relu) {
            o.x = fmaxf(o.x, 0.f); o.y = fmaxf(o.y, 0.f);
            o.z = fmaxf(o.z, 0.f); o.w = fmaxf(o.w, 0.f);
        }
        if (resid) {
            float4 rv = *(const float4*)(resid + (size_t)(row0 + i) * ldr + col0);
            o.x += rv.x; o.y += rv.y; o.z += rv.z; o.w += rv.w;
        }
        *(float4*)(C + (size_t)(row0 + i) * ldc + col0) = o;
    }
}

// ---------------- launch ----------------
extern "C" void kernel_launch(void* const* d_in, const int* in_sizes, int n_in,
                              void* d_out, int out_size) {
    (void)in_sizes; (void)n_in; (void)out_size;
    const float* x     = (const float*)d_in[0];
    const int*   mask  = (const int*  )d_in[1];
    const float* w_q   = (const float*)d_in[2];
    const float* w_k   = (const float*)d_in[3];
    const float* w_v   = (const float*)d_in[4];
    const float* w_o   = (const float*)d_in[5];
    const float* alpha1= (const float*)d_in[6];
    const float* beta1 = (const float*)d_in[7];
    const float* alpha2= (const float*)d_in[8];
    const float* beta2 = (const float*)d_in[9];
    const float* fc1_w = (const float*)d_in[10];
    const float* fc1_b = (const float*)d_in[11];
    const float* fc2_w = (const float*)d_in[12];
    const float* fc2_b = (const float*)d_in[13];
    float* out = (float*)d_out;

    float *xn, *q, *k, *v, *att, *x1, *ffh, *sc;
    cudaGetSymbolAddress((void**)&xn,  g_xn);
    cudaGetSymbolAddress((void**)&q,   g_q);
    cudaGetSymbolAddress((void**)&k,   g_k);
    cudaGetSymbolAddress((void**)&v,   g_v);
    cudaGetSymbolAddress((void**)&att, g_att);
    cudaGetSymbolAddress((void**)&x1,  g_x1);
    cudaGetSymbolAddress((void**)&ffh, g_ffh);
    cudaGetSymbolAddress((void**)&sc,  g_sc);

    const size_t sSD = (size_t)SEQ * D_MODEL;
    const size_t sSS = (size_t)SEQ * SEQ;

    // LN1
    ln_kernel<<<ROWS, 256>>>(x, alpha1, beta1, xn);

    // Q,K,V = xn @ W^T
    dim3 gQKV(D_MODEL / BN, ROWS / BM);
    gemm_kernel<true><<<gQKV, 256>>>(xn, D_MODEL, w_q, D_MODEL, q, D_MODEL,
        nullptr, nullptr, 0, ROWS, D_MODEL, D_MODEL, 1.0f, 0, 1, 0,0,0,0,0,0);
    gemm_kernel<true><<<gQKV, 256>>>(xn, D_MODEL, w_k, D_MODEL, k, D_MODEL,
        nullptr, nullptr, 0, ROWS, D_MODEL, D_MODEL, 1.0f, 0, 1, 0,0,0,0,0,0);
    gemm_kernel<true><<<gQKV, 256>>>(xn, D_MODEL, w_v, D_MODEL, v, D_MODEL,
        nullptr, nullptr, 0, ROWS, D_MODEL, D_MODEL, 1.0f, 0, 1, 0,0,0,0,0,0);

    // scores = Q @ K^T / 8 (batched over B*H)
    dim3 gSC(SEQ / BN, SEQ / BM, BATCH * NHEAD);
    gemm_kernel<true><<<gSC, 256>>>(q, D_MODEL, k, D_MODEL, sc, SEQ,
        nullptr, nullptr, 0, SEQ, SEQ, DKDIM, 0.125f, 0,
        NHEAD, sSD, DKDIM, sSD, DKDIM, (size_t)NHEAD * sSS, sSS);

    // masked softmax
    softmax_kernel<<<BATCH * NHEAD * SEQ, 256>>>(sc, mask);

    // att = P @ V (batched, NN)
    dim3 gAV(DKDIM / BN, SEQ / BM, BATCH * NHEAD);
    gemm_kernel<false><<<gAV, 256>>>(sc, SEQ, v, D_MODEL, att, D_MODEL,
        nullptr, nullptr, 0, SEQ, DKDIM, SEQ, 1.0f, 0,
        NHEAD, (size_t)NHEAD * sSS, sSS, sSD, DKDIM, sSD, DKDIM);

    // x1 = x + att @ w_o^T
    gemm_kernel<true><<<gQKV, 256>>>(att, D_MODEL, w_o, D_MODEL, x1, D_MODEL,
        nullptr, x, D_MODEL, ROWS, D_MODEL, D_MODEL, 1.0f, 0, 1, 0,0,0,0,0,0);

    // LN2
    ln_kernel<<<ROWS, 256>>>(x1, alpha2, beta2, xn);

    // ffh = relu(xn @ fc1_w^T + fc1_b)
    dim3 gFC1(D_FC / BN, ROWS / BM);
    gemm_kernel<true><<<gFC1, 256>>>(xn, D_MODEL, fc1_w, D_MODEL, ffh, D_FC,
        fc1_b, nullptr, 0, ROWS, D_FC, D_MODEL, 1.0f, 1, 1, 0,0,0,0,0,0);

    // out = x1 + ffh @ fc2_w^T + fc2_b
    dim3 gFC2(D_MODEL / BN, ROWS / BM);
    gemm_kernel<true><<<gFC2, 256>>>(ffh, D_FC, fc2_w, D_FC, out, D_MODEL,
        fc2_b, x1, D_MODEL, ROWS, D_MODEL, D_FC, 1.0f, 0, 1, 0,0,0,0,0,0);
}

// round 2
// speedup vs baseline: 1.7852x; 1.7852x over previous
#include <cuda_runtime.h>
#include <math.h>
#include <stdint.h>

#define D_MODEL 1024
#define NHEAD   16
#define DKDIM   64
#define D_FC    4096
#define BATCH   2
#define SEQ     1024
#define EPSV    1e-6f
#define ROWS    (BATCH*SEQ)

// ---------------- static device scratch (no allocations allowed) ----------------
__device__ float g_xn [(size_t)ROWS * D_MODEL];
__device__ float g_q  [(size_t)ROWS * D_MODEL];
__device__ float g_k  [(size_t)ROWS * D_MODEL];
__device__ float g_v  [(size_t)ROWS * D_MODEL];
__device__ float g_att[(size_t)ROWS * D_MODEL];
__device__ float g_x1 [(size_t)ROWS * D_MODEL];
__device__ float g_ffh[(size_t)ROWS * D_FC];
__device__ float g_sc [(size_t)BATCH * NHEAD * SEQ * SEQ];   // 128 MB scores

// ---------------- block reductions ----------------
__device__ __forceinline__ float blockReduceSum(float v, float* sbuf) {
    __syncthreads();
    #pragma unroll
    for (int o = 16; o; o >>= 1) v += __shfl_down_sync(0xFFFFFFFFu, v, o);
    int lane = threadIdx.x & 31, w = threadIdx.x >> 5;
    if (lane == 0) sbuf[w] = v;
    __syncthreads();
    if (w == 0) {
        v = (lane < (int)(blockDim.x >> 5)) ? sbuf[lane] : 0.0f;
        #pragma unroll
        for (int o = 4; o; o >>= 1) v += __shfl_down_sync(0xFFFFFFFFu, v, o);
        if (lane == 0) sbuf[0] = v;
    }
    __syncthreads();
    return sbuf[0];
}

__device__ __forceinline__ float blockReduceMax(float v, float* sbuf) {
    __syncthreads();
    #pragma unroll
    for (int o = 16; o; o >>= 1) v = fmaxf(v, __shfl_down_sync(0xFFFFFFFFu, v, o));
    int lane = threadIdx.x & 31, w = threadIdx.x >> 5;
    if (lane == 0) sbuf[w] = v;
    __syncthreads();
    if (w == 0) {
        v = (lane < (int)(blockDim.x >> 5)) ? sbuf[lane] : -3.0e38f;
        #pragma unroll
        for (int o = 4; o; o >>= 1) v = fmaxf(v, __shfl_down_sync(0xFFFFFFFFu, v, o));
        if (lane == 0) sbuf[0] = v;
    }
    __syncthreads();
    return sbuf[0];
}

// ---------------- LayerNorm (torch semantics: ddof=1, /(std+eps)) ----------------
__global__ void __launch_bounds__(256) ln_kernel(const float* __restrict__ x,
                                                 const float* __restrict__ alpha,
                                                 const float* __restrict__ beta,
                                                 float* __restrict__ out) {
    __shared__ float sbuf[32];
    size_t row = blockIdx.x;
    const float4* xr = (const float4*)(x + row * D_MODEL);
    float4 v = xr[threadIdx.x];
    float s  = v.x + v.y + v.z + v.w;
    float sq = v.x*v.x + v.y*v.y + v.z*v.z + v.w*v.w;
    float sum   = blockReduceSum(s,  sbuf);
    float sumsq = blockReduceSum(sq, sbuf);
    float mean = sum * (1.0f / D_MODEL);
    float var  = (sumsq - sum * mean) * (1.0f / (D_MODEL - 1));
    float r = 1.0f / (sqrtf(fmaxf(var, 0.0f)) + EPSV);
    float4 a = ((const float4*)alpha)[threadIdx.x];
    float4 b = ((const float4*)beta )[threadIdx.x];
    float4 o;
    o.x = a.x * (v.x - mean) * r + b.x;
    o.y = a.y * (v.y - mean) * r + b.y;
    o.z = a.z * (v.z - mean) * r + b.z;
    o.w = a.w * (v.w - mean) * r + b.w;
    ((float4*)(out + row * D_MODEL))[threadIdx.x] = o;
}

// ---------------- masked softmax over score rows ----------------
__global__ void __launch_bounds__(256) softmax_kernel(float* __restrict__ sc,
                                                      const int* __restrict__ mask) {
    __shared__ float sbuf[32];
    size_t row = blockIdx.x;
    int b = (int)(row / ((size_t)NHEAD * SEQ));
    float* p = sc + row * SEQ;
    const int* m = mask + (size_t)b * SEQ;
    int tid = threadIdx.x;
    float vals[4];
    float vmax = -3.0e38f;
    #pragma unroll
    for (int i = 0; i < 4; i++) {
        int kk = tid + i * 256;
        float v = m[kk] ? p[kk] : -1e9f;
        vals[i] = v;
        vmax = fmaxf(vmax, v);
    }
    vmax = blockReduceMax(vmax, sbuf);
    float sum = 0.0f;
    #pragma unroll
    for (int i = 0; i < 4; i++) {
        float e = __expf(vals[i] - vmax);
        vals[i] = e;
        sum += e;
    }
    sum = blockReduceSum(sum, sbuf);
    float inv = 1.0f / sum;
    #pragma unroll
    for (int i = 0; i < 4; i++) p[tid + i * 256] = vals[i] * inv;
}

// ---------------- tf32 tensor-core GEMM ----------------
// C = scale*(A @ op(B)) [+bias][relu][+resid]
// TRANSB=true : B is N x K row-major (C = A*B^T)
// TRANSB=false: B is K x N row-major (C = A*B)
// mma.sync.m16n8k8 tf32, fp32 accumulate.

__device__ __forceinline__ uint32_t f2tf32(float f) {
    uint32_t u;
    asm("cvt.rna.tf32.f32 %0, %1;" : "=r"(u) : "f"(f));
    return u;
}

__device__ __forceinline__ void mma_tf32(float* d, const uint32_t* a, const uint32_t* b) {
    asm volatile(
        "mma.sync.aligned.m16n8k8.row.col.f32.tf32.tf32.f32 "
        "{%0,%1,%2,%3}, {%4,%5,%6,%7}, {%8,%9}, {%0,%1,%2,%3};"
        : "+f"(d[0]), "+f"(d[1]), "+f"(d[2]), "+f"(d[3])
        : "r"(a[0]), "r"(a[1]), "r"(a[2]), "r"(a[3]), "r"(b[0]), "r"(b[1]));
}

template<int BM, int BN, int WARPS_M, int WARPS_N, bool TRANSB>
__global__ void __launch_bounds__(WARPS_M*WARPS_N*32) mma_gemm(
    const float* __restrict__ A, int lda,
    const float* __restrict__ B, int ldb,
    float* __restrict__ C, int ldc,
    const float* __restrict__ bias,
    const float* __restrict__ resid, int ldr,
    int K, float scale, int relu,
    int Hdiv, size_t sAb, size_t sAh, size_t sBb, size_t sBh, size_t sCb, size_t sCh)
{
    constexpr int BK = 32;
    constexpr int THREADS = WARPS_M * WARPS_N * 32;
    constexpr int WM = BM / WARPS_M;          // 64
    constexpr int WN = BN / WARPS_N;          // 32
    constexpr int MT = WM / 16;               // 4
    constexpr int NT = WN / 8;                // 4
    constexpr int LDA_S = BM + 8;             // stride ≡ 8 mod 32 -> conflict-free frag loads
    constexpr int LDB_S = BN + 8;
    constexpr int AV = (BM * BK) / (THREADS * 4);
    constexpr int BV = (BN * BK) / (THREADS * 4);

    __shared__ uint32_t As[BK][LDA_S];
    __shared__ uint32_t Bs[BK][LDB_S];

    if (gridDim.z > 1) {
        int z = blockIdx.z;
        int b = z / Hdiv, h = z - b * Hdiv;
        A += (size_t)b * sAb + (size_t)h * sAh;
        B += (size_t)b * sBb + (size_t)h * sBh;
        C += (size_t)b * sCb + (size_t)h * sCh;
    }

    const int bm = blockIdx.y * BM;
    const int bn = blockIdx.x * BN;
    const int tid  = threadIdx.x;
    const int lane = tid & 31;
    const int warp = tid >> 5;
    const int wm0 = (warp % WARPS_M) * WM;
    const int wn0 = (warp / WARPS_M) * WN;

    float acc[MT][NT][4];
    #pragma unroll
    for (int i = 0; i < MT; i++)
        #pragma unroll
        for (int j = 0; j < NT; j++)
            #pragma unroll
            for (int q = 0; q < 4; q++) acc[i][j][q] = 0.0f;

    float4 ar[AV], br[BV];

    // -------- global -> reg tile loaders --------
    auto loadA = [&](int k0) {
        #pragma unroll
        for (int i = 0; i < AV; i++) {
            int idx = tid + i * THREADS;
            int m = idx >> 3;              // BK/4 = 8 vectors per row
            int kq = (idx & 7) * 4;
            ar[i] = *(const float4*)(A + (size_t)(bm + m) * lda + k0 + kq);
        }
    };
    auto loadB = [&](int k0) {
        if (TRANSB) {
            #pragma unroll
            for (int i = 0; i < BV; i++) {
                int idx = tid + i * THREADS;
                int n = idx >> 3;
                int kq = (idx & 7) * 4;
                br[i] = *(const float4*)(B + (size_t)(bn + n) * ldb + k0 + kq);
            }
        } else {
            #pragma unroll
            for (int i = 0; i < BV; i++) {
                int idx = tid + i * THREADS;
                int krow = idx / (BN / 4);
                int nq   = (idx % (BN / 4)) * 4;
                br[i] = *(const float4*)(B + (size_t)(k0 + krow) * ldb + bn + nq);
            }
        }
    };
    auto storeTiles = [&]() {
        #pragma unroll
        for (int i = 0; i < AV; i++) {
            int idx = tid + i * THREADS;
            int m = idx >> 3;
            int kq = (idx & 7) * 4;
            As[kq + 0][m] = f2tf32(ar[i].x);
            As[kq + 1][m] = f2tf32(ar[i].y);
            As[kq + 2][m] = f2tf32(ar[i].z);
            As[kq + 3][m] = f2tf32(ar[i].w);
        }
        if (TRANSB) {
            #pragma unroll
            for (int i = 0; i < BV; i++) {
                int idx = tid + i * THREADS;
                int n = idx >> 3;
                int kq = (idx & 7) * 4;
                Bs[kq + 0][n] = f2tf32(br[i].x);
                Bs[kq + 1][n] = f2tf32(br[i].y);
                Bs[kq + 2][n] = f2tf32(br[i].z);
                Bs[kq + 3][n] = f2tf32(br[i].w);
            }
        } else {
            #pragma unroll
            for (int i = 0; i < BV; i++) {
                int idx = tid + i * THREADS;
                int krow = idx / (BN / 4);
                int nq   = (idx % (BN / 4)) * 4;
                uint4 u;
                u.x = f2tf32(br[i].x); u.y = f2tf32(br[i].y);
                u.z = f2tf32(br[i].z); u.w = f2tf32(br[i].w);
                *(uint4*)&Bs[krow][nq] = u;
            }
        }
    };

    // -------- mainloop with reg-staged double buffering --------
    loadA(0); loadB(0);
    storeTiles();
    __syncthreads();

    const int r = lane >> 2;
    const int c = lane & 3;

    for (int k0 = 0; k0 < K; k0 += BK) {
        bool more = (k0 + BK) < K;
        if (more) { loadA(k0 + BK); loadB(k0 + BK); }

        #pragma unroll
        for (int ks = 0; ks < BK; ks += 8) {
            uint32_t af[MT][4], bf[NT][2];
            #pragma unroll
            for (int mt = 0; mt < MT; mt++) {
                int m = wm0 + mt * 16 + r;
                af[mt][0] = As[ks + c    ][m];
                af[mt][1] = As[ks + c    ][m + 8];
                af[mt][2] = As[ks + c + 4][m];
                af[mt][3] = As[ks + c + 4][m + 8];
            }
            #pragma unroll
            for (int nt = 0; nt < NT; nt++) {
                int n = wn0 + nt * 8 + r;
                bf[nt][0] = Bs[ks + c    ][n];
                bf[nt][1] = Bs[ks + c + 4][n];
            }
            #pragma unroll
            for (int mt = 0; mt < MT; mt++)
                #pragma unroll
                for (int nt = 0; nt < NT; nt++)
                    mma_tf32(acc[mt][nt], af[mt], bf[nt]);
        }

        if (more) {
            __syncthreads();
            storeTiles();
            __syncthreads();
        }
    }

    // -------- epilogue --------
    #pragma unroll
    for (int mt = 0; mt < MT; mt++) {
        int row = bm + wm0 + mt * 16 + r;
        #pragma unroll
        for (int nt = 0; nt < NT; nt++) {
            int col = bn + wn0 + nt * 8 + c * 2;
            float2 bv = make_float2(0.f, 0.f);
            if (bias) bv = *(const float2*)(bias + col);
            // rows: row and row+8 ; cols: col, col+1
            #pragma unroll
            for (int half = 0; half < 2; half++) {
                int rr = row + half * 8;
                float2 o;
                o.x = acc[mt][nt][half * 2 + 0] * scale + bv.x;
                o.y = acc[mt][nt][half * 2 + 1] * scale + bv.y;
                if (relu) { o.x = fmaxf(o.x, 0.f); o.y = fmaxf(o.y, 0.f); }
                if (resid) {
                    float2 rv = *(const float2*)(resid + (size_t)rr * ldr + col);
                    o.x += rv.x; o.y += rv.y;
                }
                *(float2*)(C + (size_t)rr * ldc + col) = o;
            }
        }
    }
}

// ---------------- launch ----------------
extern "C" void kernel_launch(void* const* d_in, const int* in_sizes, int n_in,
                              void* d_out, int out_size) {
    (void)in_sizes; (void)n_in; (void)out_size;
    const float* x     = (const float*)d_in[0];
    const int*   mask  = (const int*  )d_in[1];
    const float* w_q   = (const float*)d_in[2];
    const float* w_k   = (const float*)d_in[3];
    const float* w_v   = (const float*)d_in[4];
    const float* w_o   = (const float*)d_in[5];
    const float* alpha1= (const float*)d_in[6];
    const float* beta1 = (const float*)d_in[7];
    const float* alpha2= (const float*)d_in[8];
    const float* beta2 = (const float*)d_in[9];
    const float* fc1_w = (const float*)d_in[10];
    const float* fc1_b = (const float*)d_in[11];
    const float* fc2_w = (const float*)d_in[12];
    const float* fc2_b = (const float*)d_in[13];
    float* out = (float*)d_out;

    float *xn, *q, *k, *v, *att, *x1, *ffh, *sc;
    cudaGetSymbolAddress((void**)&xn,  g_xn);
    cudaGetSymbolAddress((void**)&q,   g_q);
    cudaGetSymbolAddress((void**)&k,   g_k);
    cudaGetSymbolAddress((void**)&v,   g_v);
    cudaGetSymbolAddress((void**)&att, g_att);
    cudaGetSymbolAddress((void**)&x1,  g_x1);
    cudaGetSymbolAddress((void**)&ffh, g_ffh);
    cudaGetSymbolAddress((void**)&sc,  g_sc);

    const size_t sSD = (size_t)SEQ * D_MODEL;
    const size_t sSS = (size_t)SEQ * SEQ;

    // LN1
    ln_kernel<<<ROWS, 256>>>(x, alpha1, beta1, xn);

    // Q,K,V = xn @ W^T    (M=2048, N=1024, K=1024)
    dim3 gQKV(D_MODEL / 128, ROWS / 128);
    mma_gemm<128,128,2,4,true><<<gQKV, 256>>>(xn, D_MODEL, w_q, D_MODEL, q, D_MODEL,
        nullptr, nullptr, 0, D_MODEL, 1.0f, 0, 1, 0,0,0,0,0,0);
    mma_gemm<128,128,2,4,true><<<gQKV, 256>>>(xn, D_MODEL, w_k, D_MODEL, k, D_MODEL,
        nullptr, nullptr, 0, D_MODEL, 1.0f, 0, 1, 0,0,0,0,0,0);
    mma_gemm<128,128,2,4,true><<<gQKV, 256>>>(xn, D_MODEL, w_v, D_MODEL, v, D_MODEL,
        nullptr, nullptr, 0, D_MODEL, 1.0f, 0, 1, 0,0,0,0,0,0);

    // scores = Q @ K^T / 8   (per b,h: M=1024, N=1024, K=64)
    dim3 gSC(SEQ / 128, SEQ / 128, BATCH * NHEAD);
    mma_gemm<128,128,2,4,true><<<gSC, 256>>>(q, D_MODEL, k, D_MODEL, sc, SEQ,
        nullptr, nullptr, 0, DKDIM, 0.125f, 0,
        NHEAD, sSD, DKDIM, sSD, DKDIM, (size_t)NHEAD * sSS, sSS);

    // masked softmax
    softmax_kernel<<<BATCH * NHEAD * SEQ, 256>>>(sc, mask);

    // att = P @ V (per b,h: M=1024, N=64, K=1024), NN
    dim3 gAV(DKDIM / 64, SEQ / 128, BATCH * NHEAD);
    mma_gemm<128,64,2,2,false><<<gAV, 128>>>(sc, SEQ, v, D_MODEL, att, D_MODEL,
        nullptr, nullptr, 0, SEQ, 1.0f, 0,
        NHEAD, (size_t)NHEAD * sSS, sSS, sSD, DKDIM, sSD, DKDIM);

    // x1 = x + att @ w_o^T
    mma_gemm<128,128,2,4,true><<<gQKV, 256>>>(att, D_MODEL, w_o, D_MODEL, x1, D_MODEL,
        nullptr, x, D_MODEL, D_MODEL, 1.0f, 0, 1, 0,0,0,0,0,0);

    // LN2
    ln_kernel<<<ROWS, 256>>>(x1, alpha2, beta2, xn);

    // ffh = relu(xn @ fc1_w^T + fc1_b)   (M=2048, N=4096, K=1024)
    dim3 gFC1(D_FC / 128, ROWS / 128);
    mma_gemm<128,128,2,4,true><<<gFC1, 256>>>(xn, D_MODEL, fc1_w, D_MODEL, ffh, D_FC,
        fc1_b, nullptr, 0, D_MODEL, 1.0f, 1, 1, 0,0,0,0,0,0);

    // out = x1 + ffh @ fc2_w^T + fc2_b   (M=2048, N=1024, K=4096)
    dim3 gFC2(D_MODEL / 128, ROWS / 128);
    mma_gemm<128,128,2,4,true><<<gFC2, 256>>>(ffh, D_FC, fc2_w, D_FC, out, D_MODEL,
        fc2_b, x1, D_MODEL, D_FC, 1.0f, 0, 1, 0,0,0,0,0,0);
}

// round 3
// speedup vs baseline: 3.5340x; 1.9796x over previous
#include <cuda_runtime.h>
#include <math.h>
#include <stdint.h>

#define D_MODEL 1024
#define NHEAD   16
#define DKDIM   64
#define D_FC    4096
#define BATCH   2
#define SEQ     1024
#define EPSV    1e-6f
#define ROWS    (BATCH*SEQ)

// ---------------- static device scratch ----------------
__device__ float g_xn [(size_t)ROWS * D_MODEL];
__device__ float g_q  [(size_t)ROWS * D_MODEL];
__device__ float g_k  [(size_t)ROWS * D_MODEL];
__device__ float g_v  [(size_t)ROWS * D_MODEL];
__device__ float g_att[(size_t)ROWS * D_MODEL];
__device__ float g_x1 [(size_t)ROWS * D_MODEL];
__device__ float g_ffh[(size_t)ROWS * D_FC];

// ---------------- block reductions ----------------
__device__ __forceinline__ float blockReduceSum(float v, float* sbuf) {
    __syncthreads();
    #pragma unroll
    for (int o = 16; o; o >>= 1) v += __shfl_down_sync(0xFFFFFFFFu, v, o);
    int lane = threadIdx.x & 31, w = threadIdx.x >> 5;
    if (lane == 0) sbuf[w] = v;
    __syncthreads();
    if (w == 0) {
        v = (lane < (int)(blockDim.x >> 5)) ? sbuf[lane] : 0.0f;
        #pragma unroll
        for (int o = 4; o; o >>= 1) v += __shfl_down_sync(0xFFFFFFFFu, v, o);
        if (lane == 0) sbuf[0] = v;
    }
    __syncthreads();
    return sbuf[0];
}

// ---------------- LayerNorm (torch: ddof=1, /(std+eps)) ----------------
__global__ void __launch_bounds__(256) ln_kernel(const float* __restrict__ x,
                                                 const float* __restrict__ alpha,
                                                 const float* __restrict__ beta,
                                                 float* __restrict__ out) {
    __shared__ float sbuf[32];
    size_t row = blockIdx.x;
    float4 v = ((const float4*)(x + row * D_MODEL))[threadIdx.x];
    float s  = v.x + v.y + v.z + v.w;
    float sq = v.x*v.x + v.y*v.y + v.z*v.z + v.w*v.w;
    float sum   = blockReduceSum(s,  sbuf);
    float sumsq = blockReduceSum(sq, sbuf);
    float mean = sum * (1.0f / D_MODEL);
    float var  = (sumsq - sum * mean) * (1.0f / (D_MODEL - 1));
    float r = 1.0f / (sqrtf(fmaxf(var, 0.0f)) + EPSV);
    float4 a = ((const float4*)alpha)[threadIdx.x];
    float4 b = ((const float4*)beta )[threadIdx.x];
    float4 o;
    o.x = a.x * (v.x - mean) * r + b.x;
    o.y = a.y * (v.y - mean) * r + b.y;
    o.z = a.z * (v.z - mean) * r + b.z;
    o.w = a.w * (v.w - mean) * r + b.w;
    ((float4*)(out + row * D_MODEL))[threadIdx.x] = o;
}

// ---------------- mma helpers ----------------
__device__ __forceinline__ void mma_tf32(float* d, const uint32_t* a, const uint32_t* b) {
    asm volatile(
        "mma.sync.aligned.m16n8k8.row.col.f32.tf32.tf32.f32 "
        "{%0,%1,%2,%3}, {%4,%5,%6,%7}, {%8,%9}, {%0,%1,%2,%3};"
        : "+f"(d[0]), "+f"(d[1]), "+f"(d[2]), "+f"(d[3])
        : "r"(a[0]), "r"(a[1]), "r"(a[2]), "r"(a[3]), "r"(b[0]), "r"(b[1]));
}

__device__ __forceinline__ void cp_async16(void* smem_dst, const void* gptr) {
    uint32_t d = (uint32_t)__cvta_generic_to_shared(smem_dst);
    asm volatile("cp.async.cg.shared.global [%0], [%1], 16;" :: "r"(d), "l"(gptr));
}
#define CP_COMMIT()  asm volatile("cp.async.commit_group;")
#define CP_WAIT(N)   asm volatile("cp.async.wait_group %0;" :: "n"(N))

// ---------------- tf32 tensor-core GEMM: C = A @ B^T [+bias][relu][+resid] -----
// A: M x K row-major, B: N x K row-major. cp.async 2-stage double buffer.
// CTA 128x128x32, 8 warps (2x4), warp tile 64x32.
#define GBM 128
#define GBN 128
#define GBK 32
#define GLDK 36
#define GEMM_SMEM (2u * (GBM + GBN) * GLDK * 4u)

template<bool QKV>
__global__ void __launch_bounds__(256, 2) mma_gemm(
    const float* __restrict__ A, int lda,
    const float* __restrict__ B0, const float* __restrict__ B1, const float* __restrict__ B2,
    int ldb,
    float* __restrict__ C0, float* __restrict__ C1, float* __restrict__ C2,
    int ldc,
    const float* __restrict__ bias,
    const float* __restrict__ resid,
    int K, int relu)
{
    extern __shared__ float sm[];
    float* As = sm;                       // [2][GBM][GLDK]
    float* Bs = sm + 2 * GBM * GLDK;      // [2][GBN][GLDK]

    const float* B = B0;
    float* C = C0;
    int bn = blockIdx.x * GBN;
    if (QKV) {
        int sel = blockIdx.x >> 3;        // 8 blocks per 1024-wide weight
        B = (sel == 0) ? B0 : ((sel == 1) ? B1 : B2);
        C = (sel == 0) ? C0 : ((sel == 1) ? C1 : C2);
        bn = (blockIdx.x & 7) * GBN;
    }
    const int bm = blockIdx.y * GBM;
    const int tid  = threadIdx.x;
    const int lane = tid & 31;
    const int warp = tid >> 5;
    const int wm0 = (warp & 1) * 64;
    const int wn0 = (warp >> 1) * 32;
    const int r = lane >> 2;
    const int c = lane & 3;

    float acc[4][4][4];
    #pragma unroll
    for (int i = 0; i < 4; i++)
        #pragma unroll
        for (int j = 0; j < 4; j++)
            #pragma unroll
            for (int q = 0; q < 4; q++) acc[i][j][q] = 0.0f;

    auto loadStage = [&](int k0, int st) {
        float* Ad = As + st * GBM * GLDK;
        float* Bd = Bs + st * GBN * GLDK;
        #pragma unroll
        for (int i = 0; i < 4; i++) {
            int idx = tid + i * 256;
            int m = idx >> 3, kq = (idx & 7) * 4;
            cp_async16(Ad + m * GLDK + kq, A + (size_t)(bm + m) * lda + k0 + kq);
        }
        #pragma unroll
        for (int i = 0; i < 4; i++) {
            int idx = tid + i * 256;
            int n = idx >> 3, kq = (idx & 7) * 4;
            cp_async16(Bd + n * GLDK + kq, B + (size_t)(bn + n) * ldb + k0 + kq);
        }
    };

    auto compute = [&](int st) {
        const float* Ab = As + st * GBM * GLDK;
        const float* Bb = Bs + st * GBN * GLDK;
        #pragma unroll
        for (int ks = 0; ks < GBK; ks += 8) {
            uint32_t af[4][4], bf[4][2];
            #pragma unroll
            for (int mt = 0; mt < 4; mt++) {
                int m = wm0 + mt * 16 + r;
                af[mt][0] = __float_as_uint(Ab[(size_t)m * GLDK + ks + c]);
                af[mt][1] = __float_as_uint(Ab[(size_t)(m + 8) * GLDK + ks + c]);
                af[mt][2] = __float_as_uint(Ab[(size_t)m * GLDK + ks + c + 4]);
                af[mt][3] = __float_as_uint(Ab[(size_t)(m + 8) * GLDK + ks + c + 4]);
            }
            #pragma unroll
            for (int nt = 0; nt < 4; nt++) {
                int n = wn0 + nt * 8 + r;
                bf[nt][0] = __float_as_uint(Bb[(size_t)n * GLDK + ks + c]);
                bf[nt][1] = __float_as_uint(Bb[(size_t)n * GLDK + ks + c + 4]);
            }
            #pragma unroll
            for (int mt = 0; mt < 4; mt++)
                #pragma unroll
                for (int nt = 0; nt < 4; nt++)
                    mma_tf32(acc[mt][nt], af[mt], bf[nt]);
        }
    };

    const int kt = K / GBK;
    loadStage(0, 0);
    CP_COMMIT();
    int cur = 0;
    for (int t = 0; t < kt; t++) {
        if (t + 1 < kt) {
            loadStage((t + 1) * GBK, cur ^ 1);
            CP_COMMIT();
            CP_WAIT(1);
        } else {
            CP_WAIT(0);
        }
        __syncthreads();
        compute(cur);
        __syncthreads();
        cur ^= 1;
    }

    // epilogue
    #pragma unroll
    for (int mt = 0; mt < 4; mt++) {
        int row = bm + wm0 + mt * 16 + r;
        #pragma unroll
        for (int nt = 0; nt < 4; nt++) {
            int col = bn + wn0 + nt * 8 + c * 2;
            float2 bv = make_float2(0.f, 0.f);
            if (bias) bv = *(const float2*)(bias + col);
            #pragma unroll
            for (int half = 0; half < 2; half++) {
                int rr = row + half * 8;
                float2 o;
                o.x = acc[mt][nt][half * 2 + 0] + bv.x;
                o.y = acc[mt][nt][half * 2 + 1] + bv.y;
                if (relu) { o.x = fmaxf(o.x, 0.f); o.y = fmaxf(o.y, 0.f); }
                if (resid) {
                    float2 rv = *(const float2*)(resid + (size_t)rr * ldc + col);
                    o.x += rv.x; o.y += rv.y;
                }
                *(float2*)(C + (size_t)rr * ldc + col) = o;
            }
        }
    }
}

// ---------------- fused flash attention ----------------
// grid (SEQ/128, BATCH*NHEAD), 256 threads (8 warps x 16 q-rows).
// Per kv tile of 64: S = Q K^T /8, mask, online softmax, O += P V.
#define FLDK 68
#define FLASH_SMEM ((128*FLDK + 64*FLDK + 64*FLDK + 128*FLDK) * 4u + 64 * 4u)

__global__ void __launch_bounds__(256, 1) flash_kernel(
    const float* __restrict__ Q, const float* __restrict__ Kg,
    const float* __restrict__ Vg, const int* __restrict__ mask,
    float* __restrict__ O)
{
    extern __shared__ float sm[];
    float* Qs = sm;                         // [128][FLDK]  (q-row, d)
    float* Ks = Qs + 128 * FLDK;            // [64][FLDK]   (kv-row, d)
    float* Vs = Ks + 64 * FLDK;             // [64][FLDK]   (kv-row, d)  -> B[k][n]
    float* Ps = Vs + 64 * FLDK;             // [128][FLDK]  (q-row, kv)
    int*  msk = (int*)(Ps + 128 * FLDK);    // [64]

    const int qt = blockIdx.x;
    const int bh = blockIdx.y;
    const int b  = bh / NHEAD;
    const int h  = bh - b * NHEAD;
    const int tid  = threadIdx.x;
    const int lane = tid & 31;
    const int warp = tid >> 5;
    const int r = lane >> 2;
    const int c = lane & 3;
    const size_t rowbase = (size_t)b * SEQ + qt * 128;
    const size_t hcol = (size_t)h * DKDIM;

    // load Q tile: 128 rows x 64 d  (8 float4/thread)
    #pragma unroll
    for (int i = 0; i < 8; i++) {
        int idx = tid + i * 256;
        int m = idx >> 4, kq = (idx & 15) * 4;
        float4 v = *(const float4*)(Q + (rowbase + m) * D_MODEL + hcol + kq);
        *(float4*)(Qs + m * FLDK + kq) = v;
    }

    float m0 = -3.0e38f, m1 = -3.0e38f, l0 = 0.0f, l1 = 0.0f;
    float acc_o[8][4];
    #pragma unroll
    for (int nt = 0; nt < 8; nt++)
        #pragma unroll
        for (int q = 0; q < 4; q++) acc_o[nt][q] = 0.0f;

    const int wr = warp * 16;               // this warp's q-row base (local)

    for (int kv0 = 0; kv0 < SEQ; kv0 += 64) {
        __syncthreads();
        // load K,V tiles (4 float4/thread each) + mask
        #pragma unroll
        for (int i = 0; i < 4; i++) {
            int idx = tid + i * 256;
            int n = idx >> 4, kq = (idx & 15) * 4;
            size_t grow = (size_t)b * SEQ + kv0 + n;
            *(float4*)(Ks + n * FLDK + kq) = *(const float4*)(Kg + grow * D_MODEL + hcol + kq);
            *(float4*)(Vs + n * FLDK + kq) = *(const float4*)(Vg + grow * D_MODEL + hcol + kq);
        }
        if (tid < 64) msk[tid] = mask[(size_t)b * SEQ + kv0 + tid];
        __syncthreads();

        // ---- S = Q K^T ----
        float s[8][4];
        #pragma unroll
        for (int nt = 0; nt < 8; nt++)
            #pragma unroll
            for (int q = 0; q < 4; q++) s[nt][q] = 0.0f;

        #pragma unroll
        for (int ks = 0; ks < 64; ks += 8) {
            uint32_t af[4], bf[8][2];
            int m = wr + r;
            af[0] = __float_as_uint(Qs[(size_t)m * FLDK + ks + c]);
            af[1] = __float_as_uint(Qs[(size_t)(m + 8) * FLDK + ks + c]);
            af[2] = __float_as_uint(Qs[(size_t)m * FLDK + ks + c + 4]);
            af[3] = __float_as_uint(Qs[(size_t)(m + 8) * FLDK + ks + c + 4]);
            #pragma unroll
            for (int nt = 0; nt < 8; nt++) {
                int n = nt * 8 + r;
                bf[nt][0] = __float_as_uint(Ks[(size_t)n * FLDK + ks + c]);
                bf[nt][1] = __float_as_uint(Ks[(size_t)n * FLDK + ks + c + 4]);
            }
            #pragma unroll
            for (int nt = 0; nt < 8; nt++) mma_tf32(s[nt], af, bf[nt]);
        }

        // ---- scale + mask + tile max ----
        float tm0 = -3.0e38f, tm1 = -3.0e38f;
        #pragma unroll
        for (int nt = 0; nt < 8; nt++) {
            int col0 = nt * 8 + 2 * c;
            int mk0 = msk[col0], mk1 = msk[col0 + 1];
            s[nt][0] = mk0 ? s[nt][0] * 0.125f : -1e9f;
            s[nt][1] = mk1 ? s[nt][1] * 0.125f : -1e9f;
            s[nt][2] = mk0 ? s[nt][2] * 0.125f : -1e9f;
            s[nt][3] = mk1 ? s[nt][3] * 0.125f : -1e9f;
            tm0 = fmaxf(tm0, fmaxf(s[nt][0], s[nt][1]));
            tm1 = fmaxf(tm1, fmaxf(s[nt][2], s[nt][3]));
        }
        tm0 = fmaxf(tm0, __shfl_xor_sync(0xFFFFFFFFu, tm0, 1));
        tm0 = fmaxf(tm0, __shfl_xor_sync(0xFFFFFFFFu, tm0, 2));
        tm1 = fmaxf(tm1, __shfl_xor_sync(0xFFFFFFFFu, tm1, 1));
        tm1 = fmaxf(tm1, __shfl_xor_sync(0xFFFFFFFFu, tm1, 2));

        float mn0 = fmaxf(m0, tm0);
        float mn1 = fmaxf(m1, tm1);
        float f0 = __expf(m0 - mn0);
        float f1 = __expf(m1 - mn1);
        m0 = mn0; m1 = mn1;

        // ---- P = exp(S - m), row sums, store P ----
        float sum0 = 0.0f, sum1 = 0.0f;
        #pragma unroll
        for (int nt = 0; nt < 8; nt++) {
            float p0 = __expf(s[nt][0] - mn0);
            float p1 = __expf(s[nt][1] - mn0);
            float p2 = __expf(s[nt][2] - mn1);
            float p3 = __expf(s[nt][3] - mn1);
            sum0 += p0 + p1; sum1 += p2 + p3;
            int col0 = nt * 8 + 2 * c;
            *(float2*)(Ps + (size_t)(wr + r) * FLDK + col0)     = make_float2(p0, p1);
            *(float2*)(Ps + (size_t)(wr + r + 8) * FLDK + col0) = make_float2(p2, p3);
        }
        sum0 += __shfl_xor_sync(0xFFFFFFFFu, sum0, 1);
        sum0 += __shfl_xor_sync(0xFFFFFFFFu, sum0, 2);
        sum1 += __shfl_xor_sync(0xFFFFFFFFu, sum1, 1);
        sum1 += __shfl_xor_sync(0xFFFFFFFFu, sum1, 2);
        l0 = l0 * f0 + sum0;
        l1 = l1 * f1 + sum1;

        // rescale O accumulators
        #pragma unroll
        for (int nt = 0; nt < 8; nt++) {
            acc_o[nt][0] *= f0; acc_o[nt][1] *= f0;
            acc_o[nt][2] *= f1; acc_o[nt][3] *= f1;
        }
        __syncwarp();

        // ---- O += P V ----
        #pragma unroll
        for (int ks = 0; ks < 64; ks += 8) {
            uint32_t pf[4], vf[8][2];
            int m = wr + r;
            pf[0] = __float_as_uint(Ps[(size_t)m * FLDK + ks + c]);
            pf[1] = __float_as_uint(Ps[(size_t)(m + 8) * FLDK + ks + c]);
            pf[2] = __float_as_uint(Ps[(size_t)m * FLDK + ks + c + 4]);
            pf[3] = __float_as_uint(Ps[(size_t)(m + 8) * FLDK + ks + c + 4]);
            #pragma unroll
            for (int nt = 0; nt < 8; nt++) {
                int n = nt * 8 + r;
                vf[nt][0] = __float_as_uint(Vs[(size_t)(ks + c) * FLDK + n]);
                vf[nt][1] = __float_as_uint(Vs[(size_t)(ks + c + 4) * FLDK + n]);
            }
            #pragma unroll
            for (int nt = 0; nt < 8; nt++) mma_tf32(acc_o[nt], pf, vf[nt]);
        }
    }

    // ---- epilogue: O / l ----
    float inv0 = 1.0f / l0, inv1 = 1.0f / l1;
    size_t row0 = rowbase + wr + r;
    #pragma unroll
    for (int nt = 0; nt < 8; nt++) {
        int col = nt * 8 + 2 * c;
        *(float2*)(O + row0 * D_MODEL + hcol + col) =
            make_float2(acc_o[nt][0] * inv0, acc_o[nt][1] * inv0);
        *(float2*)(O + (row0 + 8) * D_MODEL + hcol + col) =
            make_float2(acc_o[nt][2] * inv1, acc_o[nt][3] * inv1);
    }
}

// ---------------- launch ----------------
extern "C" void kernel_launch(void* const* d_in, const int* in_sizes, int n_in,
                              void* d_out, int out_size) {
    (void)in_sizes; (void)n_in; (void)out_size;
    const float* x     = (const float*)d_in[0];
    const int*   mask  = (const int*  )d_in[1];
    const float* w_q   = (const float*)d_in[2];
    const float* w_k   = (const float*)d_in[3];
    const float* w_v   = (const float*)d_in[4];
    const float* w_o   = (const float*)d_in[5];
    const float* alpha1= (const float*)d_in[6];
    const float* beta1 = (const float*)d_in[7];
    const float* alpha2= (const float*)d_in[8];
    const float* beta2 = (const float*)d_in[9];
    const float* fc1_w = (const float*)d_in[10];
    const float* fc1_b = (const float*)d_in[11];
    const float* fc2_w = (const float*)d_in[12];
    const float* fc2_b = (const float*)d_in[13];
    float* out = (float*)d_out;

    float *xn, *q, *k, *v, *att, *x1, *ffh;
    cudaGetSymbolAddress((void**)&xn,  g_xn);
    cudaGetSymbolAddress((void**)&q,   g_q);
    cudaGetSymbolAddress((void**)&k,   g_k);
    cudaGetSymbolAddress((void**)&v,   g_v);
    cudaGetSymbolAddress((void**)&att, g_att);
    cudaGetSymbolAddress((void**)&x1,  g_x1);
    cudaGetSymbolAddress((void**)&ffh, g_ffh);

    cudaFuncSetAttribute(mma_gemm<true>,  cudaFuncAttributeMaxDynamicSharedMemorySize, GEMM_SMEM);
    cudaFuncSetAttribute(mma_gemm<false>, cudaFuncAttributeMaxDynamicSharedMemorySize, GEMM_SMEM);
    cudaFuncSetAttribute(flash_kernel,    cudaFuncAttributeMaxDynamicSharedMemorySize, FLASH_SMEM);

    // LN1
    ln_kernel<<<ROWS, 256>>>(x, alpha1, beta1, xn);

    // fused QKV: (2048 x 3072) = xn @ [w_q|w_k|w_v]^T
    mma_gemm<true><<<dim3(24, 16), 256, GEMM_SMEM>>>(
        xn, D_MODEL, w_q, w_k, w_v, D_MODEL, q, k, v, D_MODEL,
        nullptr, nullptr, D_MODEL, 0);

    // fused attention
    flash_kernel<<<dim3(SEQ / 128, BATCH * NHEAD), 256, FLASH_SMEM>>>(q, k, v, mask, att);

    // x1 = x + att @ w_o^T
    mma_gemm<false><<<dim3(8, 16), 256, GEMM_SMEM>>>(
        att, D_MODEL, w_o, nullptr, nullptr, D_MODEL, x1, nullptr, nullptr, D_MODEL,
        nullptr, x, D_MODEL, 0);

    // LN2
    ln_kernel<<<ROWS, 256>>>(x1, alpha2, beta2, xn);

    // ffh = relu(xn @ fc1_w^T + fc1_b)
    mma_gemm<false><<<dim3(32, 16), 256, GEMM_SMEM>>>(
        xn, D_MODEL, fc1_w, nullptr, nullptr, D_MODEL, ffh, nullptr, nullptr, D_FC,
        fc1_b, nullptr, D_MODEL, 1);

    // out = x1 + ffh @ fc2_w^T + fc2_b
    mma_gemm<false><<<dim3(8, 16), 256, GEMM_SMEM>>>(
        ffh, D_FC, fc2_w, nullptr, nullptr, D_FC, out, nullptr, nullptr, D_MODEL,
        fc2_b, x1, D_FC, 0);
}